// round 5
// baseline (speedup 1.0000x reference)
#include <cuda_runtime.h>
#include <math_constants.h>
#include <stdint.h>

#define NMAX 131072
#define C_DIM 1000
#define NBINS 10
#define BLOCKS 592          // 4 blocks/SM * 148 SMs -> guaranteed fully resident
#define THREADS 256

// ---- scratch (no allocations allowed) ----
// Statically initialized to the state every call expects at entry; the LAST
// ticket block restores this exact state after writing the output, so every
// graph replay sees identical initial conditions.
__device__ float g_values[NMAX];
__device__ int   g_vmax_bits = 0xFF800000;              // -inf bits
__device__ int   g_counts[NBINS] = {0};
__device__ float g_sums[NBINS]   = {0.0f};
__device__ unsigned int g_arrive = 0;                   // grid-sync arrivals
__device__ unsigned int g_ticket = 0;                   // last-block election

// ---------------------------------------------------------------------------
// Persistent fused kernel:
//   phase 1: CE values (one warp per row, single HBM pass, row in registers)
//   grid sync (all 592 blocks resident by __launch_bounds__(256,4))
//   phase 2: 10-bin histogram of values/vmax (values are L2-resident)
//   ticket:  last block computes the harmonized mean and resets globals
__global__ __launch_bounds__(THREADS, 4) void ghm_fused_kernel(
    const float* __restrict__ pred,
    const int*   __restrict__ target,   // int32 (JAX w/o x64 demotes int64 -> int32)
    int N, float* __restrict__ out)
{
    const int warp_in_blk = threadIdx.x >> 5;
    const int lane        = threadIdx.x & 31;
    const int nwarps_tot  = gridDim.x * (THREADS >> 5);
    const int warp_gid    = blockIdx.x * (THREADS >> 5) + warp_in_blk;

    __shared__ float s_wmax[8];
    __shared__ int   sc[NBINS];
    __shared__ float ss[NBINS];
    __shared__ bool  s_last;

    if (threadIdx.x < NBINS) { sc[threadIdx.x] = 0; ss[threadIdx.x] = 0.0f; }

    // ---------------- phase 1: CE values ----------------
    float wmax = -CUDART_INF_F;   // per-warp running max (valid in lane 0)

    for (int row = warp_gid; row < N; row += nwarps_tot) {
        const float4* row4 = reinterpret_cast<const float4*>(pred + (size_t)row * C_DIM);

        // Hoisted gather: issue early so its latency overlaps the reductions.
        float pt = 0.0f;
        if (lane == 0) {
            int t = target[row];
            t = min(max(t, 0), C_DIM - 1);
            pt = __ldg(pred + (size_t)row * C_DIM + t);
        }

        float4 v[8];
        float m = -CUDART_INF_F;
        #pragma unroll
        for (int j = 0; j < 8; j++) {
            int idx = lane + j * 32;            // 250 float4 per row
            if (idx < 250) {
                v[j] = row4[idx];
                m = fmaxf(m, fmaxf(fmaxf(v[j].x, v[j].y), fmaxf(v[j].z, v[j].w)));
            } else {
                v[j] = make_float4(-CUDART_INF_F, -CUDART_INF_F, -CUDART_INF_F, -CUDART_INF_F);
            }
        }
        #pragma unroll
        for (int o = 16; o > 0; o >>= 1)
            m = fmaxf(m, __shfl_xor_sync(0xFFFFFFFFu, m, o));

        float s = 0.0f;
        #pragma unroll
        for (int j = 0; j < 8; j++) {
            s += __expf(v[j].x - m);
            s += __expf(v[j].y - m);
            s += __expf(v[j].z - m);
            s += __expf(v[j].w - m);
        }
        #pragma unroll
        for (int o = 16; o > 0; o >>= 1)
            s += __shfl_xor_sync(0xFFFFFFFFu, s, o);

        if (lane == 0) {
            float val = __logf(s) + m - pt;
            g_values[row] = val;
            wmax = fmaxf(wmax, val);
        }
    }

    // one atomicMax per block for the whole kernel
    if (lane == 0) s_wmax[warp_in_blk] = wmax;
    __syncthreads();
    if (threadIdx.x == 0) {
        float bm = s_wmax[0];
        #pragma unroll
        for (int w = 1; w < 8; w++) bm = fmaxf(bm, s_wmax[w]);
        if (bm > -CUDART_INF_F)
            atomicMax(&g_vmax_bits, __float_as_int(bm));
    }

    // ---------------- grid sync (all blocks resident) ----------------
    __syncthreads();
    if (threadIdx.x == 0) {
        __threadfence();                        // publish g_values + vmax
        atomicAdd(&g_arrive, 1u);
        volatile unsigned int* p = &g_arrive;
        while (*p < (unsigned int)gridDim.x) {} // spin until all arrived
        __threadfence();                        // order subsequent reads
    }
    __syncthreads();

    // ---------------- phase 2: histogram (values are L2-hot) ----------------
    const float vmax = __int_as_float(g_vmax_bits);

    for (int i = blockIdx.x * THREADS + threadIdx.x; i < N;
         i += gridDim.x * THREADS) {
        float v  = g_values[i];
        float vc = v / vmax;
        int j = 0;
        #pragma unroll
        for (int k = 0; k <= NBINS; k++) {
            float e = (float)k / 10.0f;
            if (k == NBINS) e += 1e-6f;
            j += (vc >= e) ? 1 : 0;
        }
        int b = min(max(j - 1, 0), NBINS - 1);
        atomicAdd(&sc[b], 1);
        atomicAdd(&ss[b], v);
    }
    __syncthreads();
    if (threadIdx.x < NBINS) {
        atomicAdd(&g_counts[threadIdx.x], sc[threadIdx.x]);
        atomicAdd(&g_sums[threadIdx.x],   ss[threadIdx.x]);
    }

    // ---------------- ticket: last block finalizes + resets ----------------
    __threadfence();
    if (threadIdx.x == 0) {
        unsigned int prev = atomicAdd(&g_ticket, 1u);
        s_last = (prev == (unsigned int)(gridDim.x - 1));
    }
    __syncthreads();

    if (s_last && threadIdx.x < 32) {
        float contrib = 0.0f;
        float nne = 0.0f;
        if (lane < NBINS) {
            int   c = g_counts[lane];
            float s = g_sums[lane];
            if (c > 0) { contrib = s / (float)c; nne = 1.0f; }
        }
        #pragma unroll
        for (int o = 16; o > 0; o >>= 1) {
            contrib += __shfl_xor_sync(0xFFFFFFFFu, contrib, o);
            nne     += __shfl_xor_sync(0xFFFFFFFFu, nne, o);
        }
        if (lane == 0)
            out[0] = contrib / fmaxf(nne, 1.0f);

        // restore initial state for the next graph replay
        if (lane < NBINS) { g_counts[lane] = 0; g_sums[lane] = 0.0f; }
        if (lane == 0) {
            g_vmax_bits = 0xFF800000;
            g_ticket = 0;
            g_arrive = 0;
        }
    }
}

// ---------------------------------------------------------------------------
extern "C" void kernel_launch(void* const* d_in, const int* in_sizes, int n_in,
                              void* d_out, int out_size)
{
    const float* pred   = (const float*)d_in[0];
    const int*   target = (const int*)d_in[1];
    float*       out    = (float*)d_out;

    const int N = in_sizes[1];              // 131072 rows; C fixed at 1000

    ghm_fused_kernel<<<BLOCKS, THREADS>>>(pred, target, N, out);
}